// round 4
// baseline (speedup 1.0000x reference)
#include <cuda_runtime.h>
#include <cstdint>

// Problem constants
#define BB   64
#define DD   920
#define NSMP 920
#define KK   32
#define TOT  (BB * NSMP * DD)   // 54,169,600
#define HALF (TOT / 2)          // 27,084,800

// Scratch (static device globals -> no runtime allocation)
__device__ float g_noise[TOT];            // 216.7 MB
__device__ int   g_cnt[BB * KK * DD];     // 7.5 MB
__device__ float g_thr[BB];

// ---------------------------------------------------------------------------
// threefry2x32 helpers (JAX-exact)
// ---------------------------------------------------------------------------
__device__ __forceinline__ unsigned rotl32(unsigned x, int r) {
    return __funnelshift_l(x, x, r);
}

// bits -> float normal, matching jax.random.normal float32 path:
//   f = bitcast(bits>>9 | 0x3f800000) - 1            in [0,1)
//   u = max(lo, f*(1 - lo) + lo),  lo = nextafter(-1,0); (1-lo) rounds to 2.0f
//   n = sqrt(2) * erfinv(u)   (XLA uses the Giles polynomial)
__device__ __forceinline__ float bits_to_normal(unsigned b) {
    const float LO = -0.99999994f;  // nextafterf(-1,0)
    float f = __uint_as_float((b >> 9) | 0x3f800000u) - 1.0f;
    float u = fmaxf(LO, f * 2.0f + LO);
    float x2 = u * u;
    float w = -__logf(1.0f - x2);   // fast log: only ranking matters, ulps OK
    float p;
    if (w < 5.0f) {
        w -= 2.5f;
        p = 2.81022636e-08f;
        p = fmaf(p, w, 3.43273939e-07f);
        p = fmaf(p, w, -3.5233877e-06f);
        p = fmaf(p, w, -4.39150654e-06f);
        p = fmaf(p, w, 0.00021858087f);
        p = fmaf(p, w, -0.00125372503f);
        p = fmaf(p, w, -0.00417768164f);
        p = fmaf(p, w, 0.246640727f);
        p = fmaf(p, w, 1.50140941f);
    } else {
        w = sqrtf(w) - 3.0f;
        p = -0.000200214257f;
        p = fmaf(p, w, 0.000100950558f);
        p = fmaf(p, w, 0.00134934322f);
        p = fmaf(p, w, -0.00367342844f);
        p = fmaf(p, w, 0.00573950773f);
        p = fmaf(p, w, -0.0076224613f);
        p = fmaf(p, w, 0.00943887047f);
        p = fmaf(p, w, 1.00167406f);
        p = fmaf(p, w, 2.83297682f);
    }
    return 1.41421356f * (p * u);
}

// ---------------------------------------------------------------------------
// Kernel 0: zero the count histogram
// ---------------------------------------------------------------------------
__global__ void zero_kernel() {
    int i = blockIdx.x * blockDim.x + threadIdx.x;
    if (i < BB * KK * DD) g_cnt[i] = 0;
}

// ---------------------------------------------------------------------------
// Kernel 1: generate all normals.
// JAX threefry_2x32 on counts=iota(TOT): output[j] = x0(j, j+HALF),
// output[j+HALF] = x1(j, j+HALF), key = (0, 1).
// ---------------------------------------------------------------------------
__global__ void __launch_bounds__(256) noise_kernel() {
    unsigned j = blockIdx.x * blockDim.x + threadIdx.x;
    if (j >= HALF) return;
    const unsigned ks0 = 0u, ks1 = 1u, ks2 = 0x1BD11BDAu ^ 0u ^ 1u;
    unsigned x0 = j + ks0;
    unsigned x1 = (j + (unsigned)HALF) + ks1;
#define RND(r) { x0 += x1; x1 = rotl32(x1, r); x1 ^= x0; }
    RND(13) RND(15) RND(26) RND(6)   x0 += ks1; x1 += ks2 + 1u;
    RND(17) RND(29) RND(16) RND(24)  x0 += ks2; x1 += ks0 + 2u;
    RND(13) RND(15) RND(26) RND(6)   x0 += ks0; x1 += ks1 + 3u;
    RND(17) RND(29) RND(16) RND(24)  x0 += ks1; x1 += ks2 + 4u;
    RND(13) RND(15) RND(26) RND(6)   x0 += ks2; x1 += ks0 + 5u;
#undef RND
    g_noise[j]        = bits_to_normal(x0);
    g_noise[j + HALF] = bits_to_normal(x1);
}

// ---------------------------------------------------------------------------
// Kernel 2: per-b threshold so that count(wa > t) ~= 45
// (makes the top-k candidate window [32,64] hit on the first try almost always)
// ---------------------------------------------------------------------------
__global__ void thresh_kernel(const float* __restrict__ wa) {
    int gw = (blockIdx.x * blockDim.x + threadIdx.x) >> 5;
    int lane = threadIdx.x & 31;
    if (gw >= BB) return;
    const float* row = wa + gw * DD;
    float v[29];
#pragma unroll
    for (int s = 0; s < 29; s++) {
        int d = s * 32 + lane;
        v[s] = (d < DD) ? row[d] : -1e30f;
    }
    float tl = -1.0f, th = 2.0f;
    for (int it = 0; it < 28; it++) {
        float t = 0.5f * (tl + th);
        int lc = 0;
#pragma unroll
        for (int s = 0; s < 29; s++) lc += (v[s] > t) ? 1 : 0;
        int c = __reduce_add_sync(0xffffffffu, lc);
        if (c > 45) tl = t; else th = t;
    }
    if (lane == 0) g_thr[gw] = 0.5f * (tl + th);
}

// ---------------------------------------------------------------------------
// Kernel 3: per-row (b,n) perturbed top-32 -> count histogram.
// One warp per row; 8 warps / CTA share the smem wa row.
// ---------------------------------------------------------------------------
__global__ void __launch_bounds__(256) topk_kernel(const float* __restrict__ wa) {
    __shared__ float s_wa[DD];
    __shared__ unsigned long long s_key[8][64];
    int b = blockIdx.y;
    int warpid = threadIdx.x >> 5;
    int lane = threadIdx.x & 31;
    for (int i = threadIdx.x; i < DD; i += 256) s_wa[i] = wa[b * DD + i];
    __syncthreads();

    int n = blockIdx.x * 8 + warpid;  // gridDim.x = 115 -> n in [0,920)
    const float* nz = g_noise + ((size_t)(b * NSMP + n)) * DD;

    float v[29];
#pragma unroll
    for (int s = 0; s < 29; s++) {
        int d = s * 32 + lane;
        v[s] = (d < DD) ? (s_wa[d] + 0.1f * nz[d]) : -3.0e38f;
    }

    // find t with candidate count in [32, 64]
    float t = g_thr[b];
    float tl = -8.0f, th = 8.0f;
    int c = 0;
    for (int it = 0; it < 60; it++) {
        int lc = 0;
#pragma unroll
        for (int s = 0; s < 29; s++) lc += (v[s] > t) ? 1 : 0;
        c = __reduce_add_sync(0xffffffffu, lc);
        if (c >= 32 && c <= 64) break;
        if (c < 32) th = t; else tl = t;
        t = 0.5f * (tl + th);
    }

    // compact candidates into smem as (ordered_float << 10) | (1023 - d)
    int base = 0;
#pragma unroll
    for (int s = 0; s < 29; s++) {
        bool p = v[s] > t;
        unsigned bal = __ballot_sync(0xffffffffu, p);
        if (p) {
            int pos = base + __popc(bal & ((1u << lane) - 1u));
            if (pos < 64) {
                int d = s * 32 + lane;
                unsigned ub = __float_as_uint(v[s]);
                ub = (ub & 0x80000000u) ? ~ub : (ub | 0x80000000u);
                s_key[warpid][pos] =
                    (((unsigned long long)ub) << 10) | (unsigned long long)(1023 - d);
            }
        }
        base += __popc(bal);
    }
    __syncwarp();

    unsigned long long v0 = (lane < c) ? s_key[warpid][lane] : 0ull;
    unsigned long long v1 = (lane + 32 < c) ? s_key[warpid][lane + 32] : 0ull;

    // bitonic sort, descending, over 64 elements (pos = r*32 + lane)
#pragma unroll
    for (int k = 2; k <= 64; k <<= 1) {
#pragma unroll
        for (int j = k >> 1; j > 0; j >>= 1) {
            if (j == 32) {  // only for k == 64: pair (lane, 32+lane), keep max low
                unsigned long long mx = v0 > v1 ? v0 : v1;
                unsigned long long mn = v0 > v1 ? v1 : v0;
                v0 = mx; v1 = mn;
            } else {
                {
                    unsigned long long o = __shfl_xor_sync(0xffffffffu, v0, j);
                    bool km = ((lane & k) == 0);
                    bool lo2 = ((lane & j) == 0);
                    v0 = (km == lo2) ? (v0 > o ? v0 : o) : (v0 < o ? v0 : o);
                }
                {
                    unsigned long long o = __shfl_xor_sync(0xffffffffu, v1, j);
                    int p = 32 + lane;
                    bool km = ((p & k) == 0);
                    bool lo2 = ((lane & j) == 0);
                    v1 = (km == lo2) ? (v1 > o ? v1 : o) : (v1 < o ? v1 : o);
                }
            }
        }
    }

    // top-32 live in v0 (positions 0..31). Recover index, sort ascending.
    int d = 1023 - (int)(v0 & 1023ull);
#pragma unroll
    for (int k = 2; k <= 32; k <<= 1) {
#pragma unroll
        for (int j = k >> 1; j > 0; j >>= 1) {
            int o = __shfl_xor_sync(0xffffffffu, d, j);
            bool up = ((lane & k) == 0);
            bool lo2 = ((lane & j) == 0);
            d = (up == lo2) ? (d < o ? d : o) : (d > o ? d : o);
        }
    }
    // lane == rank i after ascending sort
    atomicAdd(&g_cnt[(b * KK + lane) * DD + d], 1);
}

// ---------------------------------------------------------------------------
// Kernel 4: s = (cnt . wa) / 920, then bbox -> out (b, k, 4)
// ---------------------------------------------------------------------------
__global__ void final_kernel(const float* __restrict__ wa, float* __restrict__ out) {
    __shared__ float s_wa[DD];
    int b = blockIdx.x;
    int warpid = threadIdx.x >> 5;
    int lane = threadIdx.x & 31;
    for (int i = threadIdx.x; i < DD; i += 256) s_wa[i] = wa[b * DD + i];
    __syncthreads();
    for (int i = warpid; i < KK; i += 8) {
        const int* cr = &g_cnt[(b * KK + i) * DD];
        float acc = 0.0f;
        for (int d = lane; d < DD; d += 32) acc += (float)cr[d] * s_wa[d];
#pragma unroll
        for (int o = 16; o; o >>= 1) acc += __shfl_xor_sync(0xffffffffu, acc, o);
        if (lane == 0) {
            float sv = acc / 920.0f;
            float r  = floorf(sv / 40.0f);
            float cc = sv - 40.0f * r;           // jnp.mod(sv, 40)
            float x0 = (cc < 1.0f ? cc : cc - 1.0f) * 32.0f;
            float y0 = (r  < 1.0f ? r  : r  - 1.0f) * 32.0f;
            float x1 = (cc < 1.0f ? cc + 2.0f : cc + 1.0f) * 32.0f;
            float y1 = (r + 2.0f) * 32.0f;
            ((float4*)out)[b * KK + i] = make_float4(x0, y0, x1, y1);
        }
    }
}

// ---------------------------------------------------------------------------
extern "C" void kernel_launch(void* const* d_in, const int* in_sizes, int n_in,
                              void* d_out, int out_size) {
    const float* wa = (const float*)d_in[2];   // weight_attn (64,23,40) -> (64,920)
    float* out = (float*)d_out;                // (64,32,4) float32

    zero_kernel<<<(BB * KK * DD + 1023) / 1024, 1024>>>();
    noise_kernel<<<(HALF + 255) / 256, 256>>>();
    thresh_kernel<<<2, 1024>>>(wa);
    topk_kernel<<<dim3(NSMP / 8, BB), 256>>>(wa);
    final_kernel<<<BB, 256>>>(wa, out);
}